// round 14
// baseline (speedup 1.0000x reference)
#include <cuda_runtime.h>
#include <cstdint>
#include <math.h>

// ---------------- problem constants ----------------
#define BB   8
#define LL   1024
#define CIN  32
#define DD   512
#define HH   8
#define DHD  64
#define DFF  2048
#define NLAYER 3
#define NCLS 16
#define UU   35
#define BL   (BB*LL)   // 8192

// ---------------- scratch (no allocations allowed) ----------------
__device__ float g_x  [BL*DD];
__device__ float g_q  [BL*DD];
__device__ float g_k  [BL*DD];
__device__ float g_v  [BL*DD];
__device__ float g_ao [BL*DD];
__device__ float g_t1 [BL*DFF];
__device__ float g_t2 [BL*DD];
__device__ float g_pe [LL*DD];
__device__ int   g_idx[LL*UU];
__device__ float g_M  [BB*HH*LL];
__device__ int   g_top[BB*HH*UU];
__device__ float g_upd[BB*HH*UU*DHD];
__device__ float g_vmean[BB*HH*DHD];

// ---------------- tf32 split (cvt.rna, cuBLAS 3xTF32 semantics) ----------------
__device__ __forceinline__ float tf32r(float x) {
    unsigned u = __float_as_uint(x), r;
    asm("cvt.rna.tf32.f32 %0, %1;" : "=r"(r) : "r"(u));
    return __uint_as_float(r);
}
__device__ __forceinline__ void split2(float v, float &hi, float &lo) {
    hi = tf32r(v);
    lo = tf32r(v - hi);
}

// ---------------- legacy tensor-core mma (sm_80+ PTX, valid at sm_100) ----------------
__device__ __forceinline__ void mma8(float4 &d, const float4 &a, float b0, float b1) {
    asm volatile(
        "mma.sync.aligned.m16n8k8.row.col.f32.tf32.tf32.f32 "
        "{%0,%1,%2,%3}, {%4,%5,%6,%7}, {%8,%9}, {%0,%1,%2,%3};"
        : "+f"(d.x), "+f"(d.y), "+f"(d.z), "+f"(d.w)
        : "r"(__float_as_uint(a.x)), "r"(__float_as_uint(a.y)),
          "r"(__float_as_uint(a.z)), "r"(__float_as_uint(a.w)),
          "r"(__float_as_uint(b0)),  "r"(__float_as_uint(b1)));
}

// ---------------- threefry-2x32 (exact JAX) ----------------
__host__ __device__ inline void tf2x32(unsigned k0, unsigned k1,
                                       unsigned x0, unsigned x1,
                                       unsigned &o0, unsigned &o1) {
    unsigned ks2 = k0 ^ k1 ^ 0x1BD11BDAu;
    unsigned v0 = x0 + k0, v1 = x1 + k1;
#define TFR(r) { v0 += v1; v1 = (v1 << (r)) | (v1 >> (32 - (r))); v1 ^= v0; }
    TFR(13) TFR(15) TFR(26) TFR(6)   v0 += k1;  v1 += ks2 + 1u;
    TFR(17) TFR(29) TFR(16) TFR(24)  v0 += ks2; v1 += k0  + 2u;
    TFR(13) TFR(15) TFR(26) TFR(6)   v0 += k0;  v1 += k1  + 3u;
    TFR(17) TFR(29) TFR(16) TFR(24)  v0 += k1;  v1 += ks2 + 4u;
    TFR(13) TFR(15) TFR(26) TFR(6)   v0 += ks2; v1 += k0  + 5u;
#undef TFR
    o0 = v0; o1 = v1;
}

// PARTITIONABLE threefry random_bits: bits[j] = o0^o1 of tf(key, 0, j); idx = bits & 1023.
__global__ void idx_kernel(unsigned k0, unsigned k1) {
    const int TOT = LL * UU;
    int j = blockIdx.x * blockDim.x + threadIdx.x;
    if (j >= TOT) return;
    unsigned o0, o1;
    tf2x32(k0, k1, 0u, (unsigned)j, o0, o1);
    g_idx[j] = (int)((o0 ^ o1) & 1023u);
}

// ---------------- positional encoding ----------------
__global__ void pe_kernel() {
    int i = blockIdx.x * blockDim.x + threadIdx.x;
    if (i >= LL * DD) return;
    int l = i / DD, d = i - l * DD;
    float earg = (float)(2 * (d >> 1)) * (float)(-9.210340371976184 / 512.0);
    float div  = (float)exp((double)earg);
    float arg  = (float)l * div;
    double a   = (double)arg;
    g_pe[i] = (d & 1) ? (float)cos(a) : (float)sin(a);
}

// ---------------- circular conv1d (k=3) embed + PE; 16 tokens per block ----------------
__global__ void __launch_bounds__(128) embed_kernel(const float* __restrict__ xe, const float* __restrict__ cw) {
    int blk = blockIdx.x;
    int tid = threadIdx.x;
    int b = blk >> 6;
    int l0 = (blk & 63) << 4;
    __shared__ float xs[18][32];
    for (int i = tid; i < 18 * 32; i += 128) {
        int r = i >> 5, c = i & 31;
        int gl = (l0 - 1 + r + LL) & (LL - 1);
        xs[r][c] = xe[((size_t)(b * LL + gl)) * CIN + c];
    }
    __syncthreads();
#pragma unroll
    for (int j = 0; j < 4; j++) {
        int d = tid + j * 128;
        const float* w = cw + (size_t)d * 96;
        float acc[16];
#pragma unroll
        for (int li = 0; li < 16; li++) acc[li] = 0.f;
        for (int c = 0; c < CIN; c++) {
#pragma unroll
            for (int t = 0; t < 3; t++) {
                float wv = w[c * 3 + t];
#pragma unroll
                for (int li = 0; li < 16; li++)
                    acc[li] = fmaf(xs[li + t][c], wv, acc[li]);
            }
        }
#pragma unroll
        for (int li = 0; li < 16; li++) {
            int l = l0 + li;
            g_x[(size_t)(b * LL + l) * DD + d] = acc[li] + g_pe[l * DD + d];
        }
    }
}

// ---------------- 3xTF32 mma.sync GEMM, raw-f32 smem + register split ----------------
// 128x128 CTA tile, 8 warps (4m x 2n), warp tile 32x64, BK=16, double buffer.
// A buffer: [2 kst][8 mtiles][128] raw f32 fragment-major         (2048 floats)
// B buffer: [2 kst][2 wn][32 lanes][20 floats (16 used + 4 pad)]  (2560 floats)
#define ABUF 2048
#define BBUF 2560
#define BUFSZ (ABUF + BBUF)   // 4608 floats per stage buffer
__global__ void __launch_bounds__(256)
gemm_mma_kernel(const float* __restrict__ A, const float* __restrict__ W,
                const float* __restrict__ bias, float* __restrict__ C,
                int M, int N, int K, int relu) {
    __shared__ __align__(16) float sm[2 * BUFSZ];   // 36 KB
    int tid = threadIdx.x, wid = tid >> 5, lane = tid & 31;
    int wm = wid >> 1, wn = wid & 1;
    int bm = blockIdx.y * 128, bn = blockIdx.x * 128;

    // producer indexing: thread covers 2 slots; slot = (row 0..127, float4 col group)
    int offA[2][4], offB[2][4];
    const float *Ag[2], *Wg[2];
#pragma unroll
    for (int i = 0; i < 2; i++) {
        int idx = tid + i * 256;
        int row = idx >> 2;
        int c4  = (idx & 3) << 2;
        Ag[i] = A + (size_t)(bm + row) * K + c4;
        Wg[i] = W + (size_t)(bn + row) * K + c4;
#pragma unroll
        for (int j = 0; j < 4; j++) {
            int c = c4 + j;
            int kst = c >> 3, cc = c & 7;
            // A raw fragment-major
            int mt = row >> 4, r = row & 15;
            int lnA = (r & 7) * 4 + (cc & 3);
            int posA = ((r >> 3) & 1) + 2 * (cc >> 2);
            offA[i][j] = kst * 1024 + mt * 128 + lnA * 4 + posA;
            // B raw per-lane runs: [kst][wnh][lane][20]: float idx = ntl*2 + half
            int ntg = row >> 3, nn8 = row & 7;
            int lnB = nn8 * 4 + (cc & 3);
            offB[i][j] = kst * 1280 + (ntg >> 3) * 640 + lnB * 20 + (ntg & 7) * 2 + (cc >> 2);
        }
    }

    float4 acc[2][8];
#pragma unroll
    for (int mt = 0; mt < 2; mt++)
#pragma unroll
        for (int nt = 0; nt < 8; nt++) acc[mt][nt] = make_float4(0.f, 0.f, 0.f, 0.f);

    float4 pa[2], pb[2];
#pragma unroll
    for (int i = 0; i < 2; i++) {
        pa[i] = *reinterpret_cast<const float4*>(Ag[i]);
        pb[i] = *reinterpret_cast<const float4*>(Wg[i]);
    }

    int NS = K / 16;
    for (int s = 0; s < NS; s++) {
        float* smA = sm + (s & 1) * BUFSZ;
        float* smB = smA + ABUF;
#pragma unroll
        for (int i = 0; i < 2; i++) {
            float av[4] = {pa[i].x, pa[i].y, pa[i].z, pa[i].w};
            float bv[4] = {pb[i].x, pb[i].y, pb[i].z, pb[i].w};
#pragma unroll
            for (int j = 0; j < 4; j++) {
                smA[offA[i][j]] = av[j];
                smB[offB[i][j]] = bv[j];
            }
        }
        __syncthreads();
        if (s + 1 < NS) {
            int off = (s + 1) * 16;
#pragma unroll
            for (int i = 0; i < 2; i++) {
                pa[i] = *reinterpret_cast<const float4*>(Ag[i] + off);
                pb[i] = *reinterpret_cast<const float4*>(Wg[i] + off);
            }
        }
#pragma unroll
        for (int kst = 0; kst < 2; kst++) {
            const float* pA = smA + kst * 1024 + (wm * 2) * 128 + lane * 4;
            float4 ra0 = *reinterpret_cast<const float4*>(pA);
            float4 ra1 = *reinterpret_cast<const float4*>(pA + 128);
            float4 ah0, al0, ah1, al1;
            split2(ra0.x, ah0.x, al0.x); split2(ra0.y, ah0.y, al0.y);
            split2(ra0.z, ah0.z, al0.z); split2(ra0.w, ah0.w, al0.w);
            split2(ra1.x, ah1.x, al1.x); split2(ra1.y, ah1.y, al1.y);
            split2(ra1.z, ah1.z, al1.z); split2(ra1.w, ah1.w, al1.w);
            const float* pB = smB + kst * 1280 + wn * 640 + lane * 20;
#pragma unroll
            for (int p = 0; p < 4; p++) {
                float4 rb = *reinterpret_cast<const float4*>(pB + p * 4);
                float bh0, bl0, bh1, bl1;
                int n0 = 2 * p, n1 = 2 * p + 1;
                split2(rb.x, bh0, bl0); split2(rb.y, bh1, bl1);
                mma8(acc[0][n0], ah0, bh0, bh1);
                mma8(acc[1][n0], ah1, bh0, bh1);
                mma8(acc[0][n0], ah0, bl0, bl1);
                mma8(acc[1][n0], ah1, bl0, bl1);
                mma8(acc[0][n0], al0, bh0, bh1);
                mma8(acc[1][n0], al1, bh0, bh1);
                split2(rb.z, bh0, bl0); split2(rb.w, bh1, bl1);
                mma8(acc[0][n1], ah0, bh0, bh1);
                mma8(acc[1][n1], ah1, bh0, bh1);
                mma8(acc[0][n1], ah0, bl0, bl1);
                mma8(acc[1][n1], ah1, bl0, bl1);
                mma8(acc[0][n1], al0, bh0, bh1);
                mma8(acc[1][n1], al1, bh0, bh1);
            }
        }
        __syncthreads();
    }

    // epilogue: bias + optional relu, STG.64
    int g = lane >> 2, tg = lane & 3;
#pragma unroll
    for (int mt = 0; mt < 2; mt++) {
        int row0 = bm + wm * 32 + mt * 16 + g;
#pragma unroll
        for (int nt = 0; nt < 8; nt++) {
            int col = bn + wn * 64 + nt * 8 + tg * 2;
            float2 bv = *reinterpret_cast<const float2*>(bias + col);
            float2 o0 = make_float2(acc[mt][nt].x + bv.x, acc[mt][nt].y + bv.y);
            float2 o1 = make_float2(acc[mt][nt].z + bv.x, acc[mt][nt].w + bv.y);
            if (relu) {
                o0.x = fmaxf(o0.x, 0.f); o0.y = fmaxf(o0.y, 0.f);
                o1.x = fmaxf(o1.x, 0.f); o1.y = fmaxf(o1.y, 0.f);
            }
            *reinterpret_cast<float2*>(C + (size_t)row0 * N + col)       = o0;
            *reinterpret_cast<float2*>(C + (size_t)(row0 + 8) * N + col) = o1;
        }
    }
}

// ---------------- M scores ----------------
__global__ void mscore_kernel() {
    int w = (blockIdx.x * blockDim.x + threadIdx.x) >> 5;
    int lane = threadIdx.x & 31;
    int l = w & (LL - 1);
    int h = (w >> 10) & (HH - 1);
    int b = w >> 13;
    const float* qr = g_q + ((size_t)(b * LL + l) * DD + h * DHD);
    float q0 = qr[lane], q1 = qr[lane + 32];
    float mx = -3.4e38f, sm = 0.f;
    for (int u = 0; u < UU; u++) {
        int ki = g_idx[l * UU + u];
        const float* kr = g_k + ((size_t)(b * LL + ki) * DD + h * DHD);
        float s = q0 * kr[lane] + q1 * kr[lane + 32];
#pragma unroll
        for (int o = 16; o > 0; o >>= 1) s += __shfl_xor_sync(0xffffffffu, s, o);
        mx = fmaxf(mx, s);
        sm += s;
    }
    if (lane == 0) g_M[w] = mx - sm * (1.0f / 1024.0f);
}

// ---------------- top-35 per (b,h) ----------------
__global__ void topk_kernel() {
    int bh = blockIdx.x, tid = threadIdx.x;   // 256
    __shared__ float sM[1024];
    __shared__ float rv[256];
    __shared__ int   ri[256];
    for (int i = tid; i < 1024; i += 256) sM[i] = g_M[bh * 1024 + i];
    __syncthreads();
    for (int u = 0; u < UU; u++) {
        float bv = -3.4e38f; int bi = 1 << 20;
#pragma unroll
        for (int j = 0; j < 4; j++) {
            int i = tid * 4 + j;
            float v = sM[i];
            if (v > bv || (v == bv && i < bi)) { bv = v; bi = i; }
        }
        rv[tid] = bv; ri[tid] = bi; __syncthreads();
        for (int st = 128; st > 0; st >>= 1) {
            if (tid < st) {
                float v2 = rv[tid + st]; int i2 = ri[tid + st];
                if (v2 > rv[tid] || (v2 == rv[tid] && i2 < ri[tid])) { rv[tid] = v2; ri[tid] = i2; }
            }
            __syncthreads();
        }
        if (tid == 0) { g_top[bh * UU + u] = ri[0]; sM[ri[0]] = -3.4e38f; }
        __syncthreads();
    }
}

// ---------------- v mean over L per (b,h,e), 4-way split ----------------
__global__ void vmean_kernel() {
    int bh = blockIdx.x;
    int tid = threadIdx.x;              // 256
    int e = tid & 63, qq = tid >> 6;
    int h = bh & 7, b = bh >> 3;
    __shared__ float red[256];
    const float* base = g_v + (size_t)b * LL * DD + h * DHD + e;
    float s = 0.f;
    for (int l = qq * 256; l < qq * 256 + 256; l++)
        s += base[(size_t)l * DD];
    red[tid] = s; __syncthreads();
    if (qq == 0)
        g_vmean[bh * DHD + e] = (red[e] + red[e + 64] + red[e + 128] + red[e + 192]) * (1.0f / 1024.0f);
}

// ---------------- full attention for selected queries ----------------
__global__ void __launch_bounds__(256) attn_kernel() {
    int blk = blockIdx.x;                    // (b*H+h)*U + u
    int u = blk % UU, bh = blk / UU;
    int h = bh & 7, b = bh >> 3;
    int tid = threadIdx.x;                   // 256
    __shared__ float qs[64];
    __shared__ float sc[1024];
    __shared__ float red[256];
    int trow = g_top[bh * UU + u];
    if (tid < 64) qs[tid] = g_q[((size_t)(b * LL + trow) * DD) + h * DHD + tid];
    __syncthreads();
    float lmax = -3.4e38f;
#pragma unroll
    for (int j = 0; j < 4; j++) {
        int k = tid + j * 256;
        const float4* kr4 = reinterpret_cast<const float4*>(g_k + ((size_t)(b * LL + k) * DD + h * DHD));
        float s = 0.f;
#pragma unroll
        for (int e4 = 0; e4 < 16; e4++) {
            float4 kv = kr4[e4];
            s = fmaf(qs[e4 * 4 + 0], kv.x, s);
            s = fmaf(qs[e4 * 4 + 1], kv.y, s);
            s = fmaf(qs[e4 * 4 + 2], kv.z, s);
            s = fmaf(qs[e4 * 4 + 3], kv.w, s);
        }
        s *= 0.125f;
        sc[k] = s;
        lmax = fmaxf(lmax, s);
    }
    red[tid] = lmax; __syncthreads();
    for (int st = 128; st > 0; st >>= 1) { if (tid < st) red[tid] = fmaxf(red[tid], red[tid + st]); __syncthreads(); }
    float bmax = red[0]; __syncthreads();
    float lsum = 0.f;
#pragma unroll
    for (int j = 0; j < 4; j++) { int k = tid + j * 256; float e = expf(sc[k] - bmax); sc[k] = e; lsum += e; }
    red[tid] = lsum; __syncthreads();
    for (int st = 128; st > 0; st >>= 1) { if (tid < st) red[tid] += red[tid + st]; __syncthreads(); }
    float inv = 1.0f / red[0]; __syncthreads();
    int e = tid & 63, cs = tid >> 6;
    float p = 0.f;
    for (int k = cs * 256; k < cs * 256 + 256; k++)
        p = fmaf(sc[k], g_v[((size_t)(b * LL + k) * DD) + h * DHD + e], p);
    red[tid] = p; __syncthreads();
    if (tid < 64) {
        float r = (red[tid] + red[tid + 64] + red[tid + 128] + red[tid + 192]) * inv;
        g_upd[((size_t)(bh * UU + u)) * DHD + tid] = r;
    }
}

// ---------------- ctx assembly ----------------
__global__ void ctxfill_kernel() {
    int i = blockIdx.x * blockDim.x + threadIdx.x;
    if (i >= BL * DD) return;
    int e = i & 63;
    int h = (i >> 16) & 7;
    int b = i >> 19;
    g_ao[i] = g_vmean[(b * HH + h) * DHD + e];
}
__global__ void scatter_kernel() {
    int blk = blockIdx.x;
    int e = threadIdx.x;                    // 64
    int u = blk % UU, bh = blk / UU;
    int trow = g_top[bh * UU + u];
    g_ao[((size_t)(bh * LL + trow)) * 64 + e] = g_upd[(size_t)blk * 64 + e];
}

// ---------------- layernorm ----------------
__global__ void ln_kernel(const float* __restrict__ add,
                          const float* __restrict__ gam, const float* __restrict__ bet) {
    int r = blockIdx.x, tid = threadIdx.x;
    __shared__ float red[256];
    size_t base = (size_t)r * DD;
    float x0 = g_x[base + tid], x1 = g_x[base + tid + 256];
    if (add) { x0 += add[base + tid]; x1 += add[base + tid + 256]; }
    red[tid] = x0 + x1; __syncthreads();
    for (int st = 128; st > 0; st >>= 1) { if (tid < st) red[tid] += red[tid + st]; __syncthreads(); }
    float m = red[0] * (1.0f / 512.0f); __syncthreads();
    float d0 = x0 - m, d1 = x1 - m;
    red[tid] = d0 * d0 + d1 * d1; __syncthreads();
    for (int st = 128; st > 0; st >>= 1) { if (tid < st) red[tid] += red[tid + st]; __syncthreads(); }
    float inv = 1.0f / sqrtf(red[0] * (1.0f / 512.0f) + 1e-5f);
    g_x[base + tid]       = d0 * inv * gam[tid]       + bet[tid];
    g_x[base + tid + 256] = d1 * inv * gam[tid + 256] + bet[tid + 256];
}

// ---------------- final fc ----------------
__global__ void final_kernel(const float* __restrict__ mark, const float* __restrict__ fcw,
                             const float* __restrict__ fcb, float* __restrict__ out) {
    int b = blockIdx.x >> 4, c = blockIdx.x & 15;
    int tid = threadIdx.x;
    __shared__ float red[256];
    const float* xr = g_x + (size_t)b * LL * DD;
    const float* wr = fcw + (size_t)c * LL * DD;
    const float* mk = mark + b * LL;
    float s = 0.f;
    for (int i = tid; i < LL * DD; i += 256)
        s = fmaf(xr[i] * mk[i >> 9], wr[i], s);
    red[tid] = s; __syncthreads();
    for (int st = 128; st > 0; st >>= 1) { if (tid < st) red[tid] += red[tid + st]; __syncthreads(); }
    if (tid == 0) out[b * NCLS + c] = red[0] + fcb[c];
}

// ---------------- host ----------------
extern "C" void kernel_launch(void* const* d_in, const int* in_sizes, int n_in,
                              void* d_out, int out_size) {
    (void)in_sizes; (void)n_in; (void)out_size;
    const float* x_enc  = (const float*)d_in[0];
    const float* x_mark = (const float*)d_in[1];
    const float* conv_w = (const float*)d_in[2];
    const float* Wq = (const float*)d_in[3];
    const float* bq = (const float*)d_in[4];
    const float* Wk = (const float*)d_in[5];
    const float* bk = (const float*)d_in[6];
    const float* Wv = (const float*)d_in[7];
    const float* bv = (const float*)d_in[8];
    const float* Wo = (const float*)d_in[9];
    const float* bo = (const float*)d_in[10];
    const float* W1 = (const float*)d_in[11];
    const float* b1 = (const float*)d_in[12];
    const float* W2 = (const float*)d_in[13];
    const float* b2 = (const float*)d_in[14];
    const float* g1 = (const float*)d_in[15];
    const float* be1= (const float*)d_in[16];
    const float* g2 = (const float*)d_in[17];
    const float* be2= (const float*)d_in[18];
    const float* gF = (const float*)d_in[19];
    const float* bF = (const float*)d_in[20];
    const float* fcw= (const float*)d_in[21];
    const float* fcb= (const float*)d_in[22];
    float* out = (float*)d_out;

    float *px, *pq, *pk, *pv, *pao, *pt1, *pt2;
    cudaGetSymbolAddress((void**)&px,  g_x);
    cudaGetSymbolAddress((void**)&pq,  g_q);
    cudaGetSymbolAddress((void**)&pk,  g_k);
    cudaGetSymbolAddress((void**)&pv,  g_v);
    cudaGetSymbolAddress((void**)&pao, g_ao);
    cudaGetSymbolAddress((void**)&pt1, g_t1);
    cudaGetSymbolAddress((void**)&pt2, g_t2);

    pe_kernel<<<(LL * DD + 255) / 256, 256>>>();
    embed_kernel<<<BL / 16, 128>>>(x_enc, conv_w);

    for (int l = 0; l < NLAYER; l++) {
        unsigned lk0, lk1;
        tf2x32(0u, 42u, 0u, (unsigned)l, lk0, lk1);
        unsigned c0, c1;
        tf2x32(lk0, lk1, 0u, 1u, c0, c1);   // second child of split(layer_key)

        gemm_mma_kernel<<<dim3(DD / 128, BL / 128), 256>>>(px, Wq + (size_t)l * DD * DD, bq + l * DD, pq, BL, DD, DD, 0);
        gemm_mma_kernel<<<dim3(DD / 128, BL / 128), 256>>>(px, Wk + (size_t)l * DD * DD, bk + l * DD, pk, BL, DD, DD, 0);
        gemm_mma_kernel<<<dim3(DD / 128, BL / 128), 256>>>(px, Wv + (size_t)l * DD * DD, bv + l * DD, pv, BL, DD, DD, 0);

        idx_kernel<<<(LL * UU + 255) / 256, 256>>>(c0, c1);
        mscore_kernel<<<(BB * HH * LL) / 8, 256>>>();
        topk_kernel<<<BB * HH, 256>>>();
        vmean_kernel<<<BB * HH, 256>>>();
        attn_kernel<<<BB * HH * UU, 256>>>();
        ctxfill_kernel<<<(BL * DD + 255) / 256, 256>>>();
        scatter_kernel<<<BB * HH * UU, 64>>>();

        gemm_mma_kernel<<<dim3(DD / 128, BL / 128), 256>>>(pao, Wo + (size_t)l * DD * DD, bo + l * DD, pt2, BL, DD, DD, 0);
        ln_kernel<<<BL, 256>>>(pt2, g1 + l * DD, be1 + l * DD);

        gemm_mma_kernel<<<dim3(DFF / 128, BL / 128), 256>>>(px, W1 + (size_t)l * DFF * DD, b1 + l * DFF, pt1, BL, DFF, DD, 1);
        gemm_mma_kernel<<<dim3(DD / 128, BL / 128), 256>>>(pt1, W2 + (size_t)l * DD * DFF, b2 + l * DD, pt2, BL, DD, DFF, 0);
        ln_kernel<<<BL, 256>>>(pt2, g2 + l * DD, be2 + l * DD);
    }

    ln_kernel<<<BL, 256>>>(nullptr, gF, bF);
    final_kernel<<<BB * NCLS, 256>>>(x_mark, fcw, fcb, out);
}

// round 15
// speedup vs baseline: 1.1144x; 1.1144x over previous
#include <cuda_runtime.h>
#include <cstdint>
#include <math.h>

// ---------------- problem constants ----------------
#define BB   8
#define LL   1024
#define CIN  32
#define DD   512
#define HH   8
#define DHD  64
#define DFF  2048
#define NLAYER 3
#define NCLS 16
#define UU   35
#define BL   (BB*LL)   // 8192

// ---------------- scratch (no allocations allowed) ----------------
__device__ float g_x  [BL*DD];
__device__ float g_q  [BL*DD];
__device__ float g_k  [BL*DD];
__device__ float g_v  [BL*DD];
__device__ float g_ao [BL*DD];
__device__ float g_t1 [BL*DFF];
__device__ float g_t2 [BL*DD];
__device__ float g_pe [LL*DD];
__device__ int   g_idx[LL*UU];
__device__ float g_M  [BB*HH*LL];
__device__ int   g_top[BB*HH*UU];
__device__ float g_upd[BB*HH*UU*DHD];
__device__ float g_vmean[BB*HH*DHD];

// ---------------- tf32 split (cvt.rna, cuBLAS 3xTF32 semantics) ----------------
__device__ __forceinline__ float tf32r(float x) {
    unsigned u = __float_as_uint(x), r;
    asm("cvt.rna.tf32.f32 %0, %1;" : "=r"(r) : "r"(u));
    return __uint_as_float(r);
}
__device__ __forceinline__ void split2(float v, float &hi, float &lo) {
    hi = tf32r(v);
    lo = tf32r(v - hi);
}

// ---------------- legacy tensor-core mma (sm_80+ PTX, valid at sm_100) ----------------
__device__ __forceinline__ void mma8(float4 &d, const float4 &a, float b0, float b1) {
    asm volatile(
        "mma.sync.aligned.m16n8k8.row.col.f32.tf32.tf32.f32 "
        "{%0,%1,%2,%3}, {%4,%5,%6,%7}, {%8,%9}, {%0,%1,%2,%3};"
        : "+f"(d.x), "+f"(d.y), "+f"(d.z), "+f"(d.w)
        : "r"(__float_as_uint(a.x)), "r"(__float_as_uint(a.y)),
          "r"(__float_as_uint(a.z)), "r"(__float_as_uint(a.w)),
          "r"(__float_as_uint(b0)),  "r"(__float_as_uint(b1)));
}

// ---------------- threefry-2x32 (exact JAX) ----------------
__host__ __device__ inline void tf2x32(unsigned k0, unsigned k1,
                                       unsigned x0, unsigned x1,
                                       unsigned &o0, unsigned &o1) {
    unsigned ks2 = k0 ^ k1 ^ 0x1BD11BDAu;
    unsigned v0 = x0 + k0, v1 = x1 + k1;
#define TFR(r) { v0 += v1; v1 = (v1 << (r)) | (v1 >> (32 - (r))); v1 ^= v0; }
    TFR(13) TFR(15) TFR(26) TFR(6)   v0 += k1;  v1 += ks2 + 1u;
    TFR(17) TFR(29) TFR(16) TFR(24)  v0 += ks2; v1 += k0  + 2u;
    TFR(13) TFR(15) TFR(26) TFR(6)   v0 += k0;  v1 += k1  + 3u;
    TFR(17) TFR(29) TFR(16) TFR(24)  v0 += k1;  v1 += ks2 + 4u;
    TFR(13) TFR(15) TFR(26) TFR(6)   v0 += ks2; v1 += k0  + 5u;
#undef TFR
    o0 = v0; o1 = v1;
}

// PARTITIONABLE threefry random_bits: bits[j] = o0^o1 of tf(key, 0, j); idx = bits & 1023.
__global__ void idx_kernel(unsigned k0, unsigned k1) {
    const int TOT = LL * UU;
    int j = blockIdx.x * blockDim.x + threadIdx.x;
    if (j >= TOT) return;
    unsigned o0, o1;
    tf2x32(k0, k1, 0u, (unsigned)j, o0, o1);
    g_idx[j] = (int)((o0 ^ o1) & 1023u);
}

// ---------------- positional encoding ----------------
__global__ void pe_kernel() {
    int i = blockIdx.x * blockDim.x + threadIdx.x;
    if (i >= LL * DD) return;
    int l = i / DD, d = i - l * DD;
    float earg = (float)(2 * (d >> 1)) * (float)(-9.210340371976184 / 512.0);
    float div  = (float)exp((double)earg);
    float arg  = (float)l * div;
    double a   = (double)arg;
    g_pe[i] = (d & 1) ? (float)cos(a) : (float)sin(a);
}

// ---------------- circular conv1d (k=3) embed + PE; 16 tokens per block ----------------
__global__ void __launch_bounds__(128) embed_kernel(const float* __restrict__ xe, const float* __restrict__ cw) {
    int blk = blockIdx.x;
    int tid = threadIdx.x;
    int b = blk >> 6;
    int l0 = (blk & 63) << 4;
    __shared__ float xs[18][32];
    for (int i = tid; i < 18 * 32; i += 128) {
        int r = i >> 5, c = i & 31;
        int gl = (l0 - 1 + r + LL) & (LL - 1);
        xs[r][c] = xe[((size_t)(b * LL + gl)) * CIN + c];
    }
    __syncthreads();
#pragma unroll
    for (int j = 0; j < 4; j++) {
        int d = tid + j * 128;
        const float* w = cw + (size_t)d * 96;
        float acc[16];
#pragma unroll
        for (int li = 0; li < 16; li++) acc[li] = 0.f;
        for (int c = 0; c < CIN; c++) {
#pragma unroll
            for (int t = 0; t < 3; t++) {
                float wv = w[c * 3 + t];
#pragma unroll
                for (int li = 0; li < 16; li++)
                    acc[li] = fmaf(xs[li + t][c], wv, acc[li]);
            }
        }
#pragma unroll
        for (int li = 0; li < 16; li++) {
            int l = l0 + li;
            g_x[(size_t)(b * LL + l) * DD + d] = acc[li] + g_pe[l * DD + d];
        }
    }
}

// ---------------- 3xTF32 mma.sync GEMM, pass-major pipelined ----------------
// 128x128 CTA tile, 8 warps (4m x 2n), warp tile 32x64, BK=16, double buffer.
// A buffer: [2 kst][8 mtiles][128] raw f32 fragment-major         (2048 floats)
// B buffer: [2 kst][2 wn][32 lanes][20 floats (16 used + 4 pad)]  (2560 floats)
// Consumer: per kst, pass-major (hh x16, hl x16, lh x16) -> acc reuse distance 16 MMAs.
#define ABUF 2048
#define BBUF 2560
#define BUFSZ (ABUF + BBUF)   // 4608 floats per stage buffer
__global__ void __launch_bounds__(256, 2)
gemm_mma_kernel(const float* __restrict__ A, const float* __restrict__ W,
                const float* __restrict__ bias, float* __restrict__ C,
                int M, int N, int K, int relu) {
    __shared__ __align__(16) float sm[2 * BUFSZ];   // 36 KB
    int tid = threadIdx.x, wid = tid >> 5, lane = tid & 31;
    int wm = wid >> 1, wn = wid & 1;
    int bm = blockIdx.y * 128, bn = blockIdx.x * 128;

    // producer indexing: thread covers 2 slots; offsets are affine in j:
    //   offA(i,j) = offA0[i] + j*4 ; offB(i,j) = offB0[i] + j*20
    int offA0[2], offB0[2];
    const float *Ag[2], *Wg[2];
#pragma unroll
    for (int i = 0; i < 2; i++) {
        int idx = tid + i * 256;
        int row = idx >> 2;
        int c4  = (idx & 3) << 2;
        Ag[i] = A + (size_t)(bm + row) * K + c4;
        Wg[i] = W + (size_t)(bn + row) * K + c4;
        int kst = c4 >> 3, cc = c4 & 7;
        int mt = row >> 4, r = row & 15;
        int lnA = (r & 7) * 4;                       // (cc&3)=0 at j=0
        int posA = ((r >> 3) & 1) + 2 * (cc >> 2);
        offA0[i] = kst * 1024 + mt * 128 + lnA * 4 + posA;
        int ntg = row >> 3, nn8 = row & 7;
        int lnB = nn8 * 4;
        offB0[i] = kst * 1280 + (ntg >> 3) * 640 + lnB * 20 + (ntg & 7) * 2 + (cc >> 2);
    }

    float4 acc[2][8];
#pragma unroll
    for (int mt = 0; mt < 2; mt++)
#pragma unroll
        for (int nt = 0; nt < 8; nt++) acc[mt][nt] = make_float4(0.f, 0.f, 0.f, 0.f);

    float4 pa[2], pb[2];
#pragma unroll
    for (int i = 0; i < 2; i++) {
        pa[i] = *reinterpret_cast<const float4*>(Ag[i]);
        pb[i] = *reinterpret_cast<const float4*>(Wg[i]);
    }

    int NS = K / 16;
    for (int s = 0; s < NS; s++) {
        float* smA = sm + (s & 1) * BUFSZ;
        float* smB = smA + ABUF;
#pragma unroll
        for (int i = 0; i < 2; i++) {
            float av[4] = {pa[i].x, pa[i].y, pa[i].z, pa[i].w};
            float bv[4] = {pb[i].x, pb[i].y, pb[i].z, pb[i].w};
#pragma unroll
            for (int j = 0; j < 4; j++) {
                smA[offA0[i] + j * 4]  = av[j];
                smB[offB0[i] + j * 20] = bv[j];
            }
        }
        __syncthreads();
        if (s + 1 < NS) {
            int off = (s + 1) * 16;
#pragma unroll
            for (int i = 0; i < 2; i++) {
                pa[i] = *reinterpret_cast<const float4*>(Ag[i] + off);
                pb[i] = *reinterpret_cast<const float4*>(Wg[i] + off);
            }
        }
#pragma unroll
        for (int kst = 0; kst < 2; kst++) {
            const float* pA = smA + kst * 1024 + (wm * 2) * 128 + lane * 4;
            float4 ra0 = *reinterpret_cast<const float4*>(pA);
            float4 ra1 = *reinterpret_cast<const float4*>(pA + 128);
            float4 ah0, al0, ah1, al1;
            split2(ra0.x, ah0.x, al0.x); split2(ra0.y, ah0.y, al0.y);
            split2(ra0.z, ah0.z, al0.z); split2(ra0.w, ah0.w, al0.w);
            split2(ra1.x, ah1.x, al1.x); split2(ra1.y, ah1.y, al1.y);
            split2(ra1.z, ah1.z, al1.z); split2(ra1.w, ah1.w, al1.w);
            const float* pB = smB + kst * 1280 + wn * 640 + lane * 20;
            float4 rb[4];
#pragma unroll
            for (int p = 0; p < 4; p++) rb[p] = *reinterpret_cast<const float4*>(pB + p * 4);

            // pass 1: hi*hi  (16 independent MMAs)
#pragma unroll
            for (int p = 0; p < 4; p++) {
                float h0, h1, t;
                h0 = tf32r(rb[p].x); h1 = tf32r(rb[p].y); (void)t;
                mma8(acc[0][2 * p], ah0, h0, h1);
                mma8(acc[1][2 * p], ah1, h0, h1);
                h0 = tf32r(rb[p].z); h1 = tf32r(rb[p].w);
                mma8(acc[0][2 * p + 1], ah0, h0, h1);
                mma8(acc[1][2 * p + 1], ah1, h0, h1);
            }
            // pass 2: hi_A * lo_B
#pragma unroll
            for (int p = 0; p < 4; p++) {
                float h, l0, l1;
                split2(rb[p].x, h, l0); split2(rb[p].y, h, l1);
                mma8(acc[0][2 * p], ah0, l0, l1);
                mma8(acc[1][2 * p], ah1, l0, l1);
                split2(rb[p].z, h, l0); split2(rb[p].w, h, l1);
                mma8(acc[0][2 * p + 1], ah0, l0, l1);
                mma8(acc[1][2 * p + 1], ah1, l0, l1);
            }
            // pass 3: lo_A * hi_B
#pragma unroll
            for (int p = 0; p < 4; p++) {
                float h0, h1;
                h0 = tf32r(rb[p].x); h1 = tf32r(rb[p].y);
                mma8(acc[0][2 * p], al0, h0, h1);
                mma8(acc[1][2 * p], al1, h0, h1);
                h0 = tf32r(rb[p].z); h1 = tf32r(rb[p].w);
                mma8(acc[0][2 * p + 1], al0, h0, h1);
                mma8(acc[1][2 * p + 1], al1, h0, h1);
            }
        }
        __syncthreads();
    }

    // epilogue: bias + optional relu, STG.64
    int g = lane >> 2, tg = lane & 3;
#pragma unroll
    for (int mt = 0; mt < 2; mt++) {
        int row0 = bm + wm * 32 + mt * 16 + g;
#pragma unroll
        for (int nt = 0; nt < 8; nt++) {
            int col = bn + wn * 64 + nt * 8 + tg * 2;
            float2 bv = *reinterpret_cast<const float2*>(bias + col);
            float2 o0 = make_float2(acc[mt][nt].x + bv.x, acc[mt][nt].y + bv.y);
            float2 o1 = make_float2(acc[mt][nt].z + bv.x, acc[mt][nt].w + bv.y);
            if (relu) {
                o0.x = fmaxf(o0.x, 0.f); o0.y = fmaxf(o0.y, 0.f);
                o1.x = fmaxf(o1.x, 0.f); o1.y = fmaxf(o1.y, 0.f);
            }
            *reinterpret_cast<float2*>(C + (size_t)row0 * N + col)       = o0;
            *reinterpret_cast<float2*>(C + (size_t)(row0 + 8) * N + col) = o1;
        }
    }
}

// ---------------- M scores ----------------
__global__ void mscore_kernel() {
    int w = (blockIdx.x * blockDim.x + threadIdx.x) >> 5;
    int lane = threadIdx.x & 31;
    int l = w & (LL - 1);
    int h = (w >> 10) & (HH - 1);
    int b = w >> 13;
    const float* qr = g_q + ((size_t)(b * LL + l) * DD + h * DHD);
    float q0 = qr[lane], q1 = qr[lane + 32];
    float mx = -3.4e38f, sm = 0.f;
    for (int u = 0; u < UU; u++) {
        int ki = g_idx[l * UU + u];
        const float* kr = g_k + ((size_t)(b * LL + ki) * DD + h * DHD);
        float s = q0 * kr[lane] + q1 * kr[lane + 32];
#pragma unroll
        for (int o = 16; o > 0; o >>= 1) s += __shfl_xor_sync(0xffffffffu, s, o);
        mx = fmaxf(mx, s);
        sm += s;
    }
    if (lane == 0) g_M[w] = mx - sm * (1.0f / 1024.0f);
}

// ---------------- top-35 per (b,h) ----------------
__global__ void topk_kernel() {
    int bh = blockIdx.x, tid = threadIdx.x;   // 256
    __shared__ float sM[1024];
    __shared__ float rv[256];
    __shared__ int   ri[256];
    for (int i = tid; i < 1024; i += 256) sM[i] = g_M[bh * 1024 + i];
    __syncthreads();
    for (int u = 0; u < UU; u++) {
        float bv = -3.4e38f; int bi = 1 << 20;
#pragma unroll
        for (int j = 0; j < 4; j++) {
            int i = tid * 4 + j;
            float v = sM[i];
            if (v > bv || (v == bv && i < bi)) { bv = v; bi = i; }
        }
        rv[tid] = bv; ri[tid] = bi; __syncthreads();
        for (int st = 128; st > 0; st >>= 1) {
            if (tid < st) {
                float v2 = rv[tid + st]; int i2 = ri[tid + st];
                if (v2 > rv[tid] || (v2 == rv[tid] && i2 < ri[tid])) { rv[tid] = v2; ri[tid] = i2; }
            }
            __syncthreads();
        }
        if (tid == 0) { g_top[bh * UU + u] = ri[0]; sM[ri[0]] = -3.4e38f; }
        __syncthreads();
    }
}

// ---------------- v mean over L per (b,h,e), 4-way split ----------------
__global__ void vmean_kernel() {
    int bh = blockIdx.x;
    int tid = threadIdx.x;              // 256
    int e = tid & 63, qq = tid >> 6;
    int h = bh & 7, b = bh >> 3;
    __shared__ float red[256];
    const float* base = g_v + (size_t)b * LL * DD + h * DHD + e;
    float s = 0.f;
    for (int l = qq * 256; l < qq * 256 + 256; l++)
        s += base[(size_t)l * DD];
    red[tid] = s; __syncthreads();
    if (qq == 0)
        g_vmean[bh * DHD + e] = (red[e] + red[e + 64] + red[e + 128] + red[e + 192]) * (1.0f / 1024.0f);
}

// ---------------- full attention for selected queries ----------------
__global__ void __launch_bounds__(256) attn_kernel() {
    int blk = blockIdx.x;                    // (b*H+h)*U + u
    int u = blk % UU, bh = blk / UU;
    int h = bh & 7, b = bh >> 3;
    int tid = threadIdx.x;                   // 256
    __shared__ float qs[64];
    __shared__ float sc[1024];
    __shared__ float red[256];
    int trow = g_top[bh * UU + u];
    if (tid < 64) qs[tid] = g_q[((size_t)(b * LL + trow) * DD) + h * DHD + tid];
    __syncthreads();
    float lmax = -3.4e38f;
#pragma unroll
    for (int j = 0; j < 4; j++) {
        int k = tid + j * 256;
        const float4* kr4 = reinterpret_cast<const float4*>(g_k + ((size_t)(b * LL + k) * DD + h * DHD));
        float s = 0.f;
#pragma unroll
        for (int e4 = 0; e4 < 16; e4++) {
            float4 kv = kr4[e4];
            s = fmaf(qs[e4 * 4 + 0], kv.x, s);
            s = fmaf(qs[e4 * 4 + 1], kv.y, s);
            s = fmaf(qs[e4 * 4 + 2], kv.z, s);
            s = fmaf(qs[e4 * 4 + 3], kv.w, s);
        }
        s *= 0.125f;
        sc[k] = s;
        lmax = fmaxf(lmax, s);
    }
    red[tid] = lmax; __syncthreads();
    for (int st = 128; st > 0; st >>= 1) { if (tid < st) red[tid] = fmaxf(red[tid], red[tid + st]); __syncthreads(); }
    float bmax = red[0]; __syncthreads();
    float lsum = 0.f;
#pragma unroll
    for (int j = 0; j < 4; j++) { int k = tid + j * 256; float e = expf(sc[k] - bmax); sc[k] = e; lsum += e; }
    red[tid] = lsum; __syncthreads();
    for (int st = 128; st > 0; st >>= 1) { if (tid < st) red[tid] += red[tid + st]; __syncthreads(); }
    float inv = 1.0f / red[0]; __syncthreads();
    int e = tid & 63, cs = tid >> 6;
    float p = 0.f;
    for (int k = cs * 256; k < cs * 256 + 256; k++)
        p = fmaf(sc[k], g_v[((size_t)(b * LL + k) * DD) + h * DHD + e], p);
    red[tid] = p; __syncthreads();
    if (tid < 64) {
        float r = (red[tid] + red[tid + 64] + red[tid + 128] + red[tid + 192]) * inv;
        g_upd[((size_t)(bh * UU + u)) * DHD + tid] = r;
    }
}

// ---------------- ctx assembly ----------------
__global__ void ctxfill_kernel() {
    int i = blockIdx.x * blockDim.x + threadIdx.x;
    if (i >= BL * DD) return;
    int e = i & 63;
    int h = (i >> 16) & 7;
    int b = i >> 19;
    g_ao[i] = g_vmean[(b * HH + h) * DHD + e];
}
__global__ void scatter_kernel() {
    int blk = blockIdx.x;
    int e = threadIdx.x;                    // 64
    int u = blk % UU, bh = blk / UU;
    int trow = g_top[bh * UU + u];
    g_ao[((size_t)(bh * LL + trow)) * 64 + e] = g_upd[(size_t)blk * 64 + e];
}

// ---------------- layernorm ----------------
__global__ void ln_kernel(const float* __restrict__ add,
                          const float* __restrict__ gam, const float* __restrict__ bet) {
    int r = blockIdx.x, tid = threadIdx.x;
    __shared__ float red[256];
    size_t base = (size_t)r * DD;
    float x0 = g_x[base + tid], x1 = g_x[base + tid + 256];
    if (add) { x0 += add[base + tid]; x1 += add[base + tid + 256]; }
    red[tid] = x0 + x1; __syncthreads();
    for (int st = 128; st > 0; st >>= 1) { if (tid < st) red[tid] += red[tid + st]; __syncthreads(); }
    float m = red[0] * (1.0f / 512.0f); __syncthreads();
    float d0 = x0 - m, d1 = x1 - m;
    red[tid] = d0 * d0 + d1 * d1; __syncthreads();
    for (int st = 128; st > 0; st >>= 1) { if (tid < st) red[tid] += red[tid + st]; __syncthreads(); }
    float inv = 1.0f / sqrtf(red[0] * (1.0f / 512.0f) + 1e-5f);
    g_x[base + tid]       = d0 * inv * gam[tid]       + bet[tid];
    g_x[base + tid + 256] = d1 * inv * gam[tid + 256] + bet[tid + 256];
}

// ---------------- final fc ----------------
__global__ void final_kernel(const float* __restrict__ mark, const float* __restrict__ fcw,
                             const float* __restrict__ fcb, float* __restrict__ out) {
    int b = blockIdx.x >> 4, c = blockIdx.x & 15;
    int tid = threadIdx.x;
    __shared__ float red[256];
    const float* xr = g_x + (size_t)b * LL * DD;
    const float* wr = fcw + (size_t)c * LL * DD;
    const float* mk = mark + b * LL;
    float s = 0.f;
    for (int i = tid; i < LL * DD; i += 256)
        s = fmaf(xr[i] * mk[i >> 9], wr[i], s);
    red[tid] = s; __syncthreads();
    for (int st = 128; st > 0; st >>= 1) { if (tid < st) red[tid] += red[tid + st]; __syncthreads(); }
    if (tid == 0) out[b * NCLS + c] = red[0] + fcb[c];
}

// ---------------- host ----------------
extern "C" void kernel_launch(void* const* d_in, const int* in_sizes, int n_in,
                              void* d_out, int out_size) {
    (void)in_sizes; (void)n_in; (void)out_size;
    const float* x_enc  = (const float*)d_in[0];
    const float* x_mark = (const float*)d_in[1];
    const float* conv_w = (const float*)d_in[2];
    const float* Wq = (const float*)d_in[3];
    const float* bq = (const float*)d_in[4];
    const float* Wk = (const float*)d_in[5];
    const float* bk = (const float*)d_in[6];
    const float* Wv = (const float*)d_in[7];
    const float* bv = (const float*)d_in[8];
    const float* Wo = (const float*)d_in[9];
    const float* bo = (const float*)d_in[10];
    const float* W1 = (const float*)d_in[11];
    const float* b1 = (const float*)d_in[12];
    const float* W2 = (const float*)d_in[13];
    const float* b2 = (const float*)d_in[14];
    const float* g1 = (const float*)d_in[15];
    const float* be1= (const float*)d_in[16];
    const float* g2 = (const float*)d_in[17];
    const float* be2= (const float*)d_in[18];
    const float* gF = (const float*)d_in[19];
    const float* bF = (const float*)d_in[20];
    const float* fcw= (const float*)d_in[21];
    const float* fcb= (const float*)d_in[22];
    float* out = (float*)d_out;

    float *px, *pq, *pk, *pv, *pao, *pt1, *pt2;
    cudaGetSymbolAddress((void**)&px,  g_x);
    cudaGetSymbolAddress((void**)&pq,  g_q);
    cudaGetSymbolAddress((void**)&pk,  g_k);
    cudaGetSymbolAddress((void**)&pv,  g_v);
    cudaGetSymbolAddress((void**)&pao, g_ao);
    cudaGetSymbolAddress((void**)&pt1, g_t1);
    cudaGetSymbolAddress((void**)&pt2, g_t2);

    pe_kernel<<<(LL * DD + 255) / 256, 256>>>();
    embed_kernel<<<BL / 16, 128>>>(x_enc, conv_w);

    for (int l = 0; l < NLAYER; l++) {
        unsigned lk0, lk1;
        tf2x32(0u, 42u, 0u, (unsigned)l, lk0, lk1);
        unsigned c0, c1;
        tf2x32(lk0, lk1, 0u, 1u, c0, c1);   // second child of split(layer_key)

        gemm_mma_kernel<<<dim3(DD / 128, BL / 128), 256>>>(px, Wq + (size_t)l * DD * DD, bq + l * DD, pq, BL, DD, DD, 0);
        gemm_mma_kernel<<<dim3(DD / 128, BL / 128), 256>>>(px, Wk + (size_t)l * DD * DD, bk + l * DD, pk, BL, DD, DD, 0);
        gemm_mma_kernel<<<dim3(DD / 128, BL / 128), 256>>>(px, Wv + (size_t)l * DD * DD, bv + l * DD, pv, BL, DD, DD, 0);

        idx_kernel<<<(LL * UU + 255) / 256, 256>>>(c0, c1);
        mscore_kernel<<<(BB * HH * LL) / 8, 256>>>();
        topk_kernel<<<BB * HH, 256>>>();
        vmean_kernel<<<BB * HH, 256>>>();
        attn_kernel<<<BB * HH * UU, 256>>>();
        ctxfill_kernel<<<(BL * DD + 255) / 256, 256>>>();
        scatter_kernel<<<BB * HH * UU, 64>>>();

        gemm_mma_kernel<<<dim3(DD / 128, BL / 128), 256>>>(pao, Wo + (size_t)l * DD * DD, bo + l * DD, pt2, BL, DD, DD, 0);
        ln_kernel<<<BL, 256>>>(pt2, g1 + l * DD, be1 + l * DD);

        gemm_mma_kernel<<<dim3(DFF / 128, BL / 128), 256>>>(px, W1 + (size_t)l * DFF * DD, b1 + l * DFF, pt1, BL, DFF, DD, 1);
        gemm_mma_kernel<<<dim3(DD / 128, BL / 128), 256>>>(pt1, W2 + (size_t)l * DD * DFF, b2 + l * DD, pt2, BL, DD, DFF, 0);
        ln_kernel<<<BL, 256>>>(pt2, g2 + l * DD, be2 + l * DD);
    }

    ln_kernel<<<BL, 256>>>(nullptr, gF, bF);
    final_kernel<<<BB * NCLS, 256>>>(x_mark, fcw, fcb, out);
}